// round 12
// baseline (speedup 1.0000x reference)
#include <cuda_runtime.h>
#include <cuda_fp16.h>
#include <cstdint>

#define BATCH 4
#define SLEN  4096
#define HID   1024
#define MTOT  (BATCH * SLEN)   // 16384

// ---------------- static scratch (no runtime allocation) ----------------
__device__ __align__(16) __half g_xh[(size_t)MTOT * HID];
__device__ __align__(16) __half g_xl[(size_t)MTOT * HID];
__device__ __align__(16) __half g_wf[3][(size_t)HID * HID];  // Wq,Wk,Wv fp16 planes
__device__ __align__(16) __half g_qf[(size_t)MTOT * HID];    // q fp16 plane
__device__ __align__(16) __half g_kf[(size_t)MTOT * HID];    // k fp16 plane
__device__ __align__(16) __half g_vt[(size_t)MTOT * HID];    // v^T [b][h][s]
__device__ __align__(16) __half g_pf[(size_t)MTOT * SLEN];   // p fp16, zero-padded
__device__ __align__(16) __half g_Sh[(size_t)BATCH * SLEN * SLEN];  // scaled scores fp16

// ---------------- common helpers ----------------
__device__ __forceinline__ uint32_t smem_u32(const void* p) {
    return (uint32_t)__cvta_generic_to_shared(p);
}
#define CP_ASYNC16(dst, src) \
    asm volatile("cp.async.cg.shared.global [%0], [%1], 16;" :: "r"(dst), "l"(src) : "memory")
#define LDMX4(R0, R1, R2, R3, addr)                                              \
    asm volatile("ldmatrix.sync.aligned.m8n8.x4.shared.b16 {%0,%1,%2,%3}, [%4];" \
                 : "=r"(R0), "=r"(R1), "=r"(R2), "=r"(R3) : "r"(addr))
#define MMAF16(C, A0, A1, A2, A3, B0, B1)                                      \
    asm volatile("mma.sync.aligned.m16n8k16.row.col.f32.f16.f16.f32 "          \
                 "{%0,%1,%2,%3}, {%4,%5,%6,%7}, {%8,%9}, {%0,%1,%2,%3};"       \
                 : "+f"(C[0]), "+f"(C[1]), "+f"(C[2]), "+f"(C[3])              \
                 : "r"(A0), "r"(A1), "r"(A2), "r"(A3), "r"(B0), "r"(B1))

#define CHUNK_K 64   // 4 ks-steps per chunk; halves barrier count vs 32

// =================================================================================
// Engine 2 (projections): C = (A_hi + A_lo) . B^T, B single fp16 plane.
// 256 thr, warps 4m x 2n (warp tile 32x64), 2-stage, occ 2.
// A rows: 272B [hi 128 | lo 128 | pad 16] (68-word stride, conflict-free ldmatrix).
// B rows: 144B [128 data | 16 pad].
// =================================================================================
#define E2_SMO_B   34816                 // 128*272
#define E2_STAGE   53248                 // + 128*144
#define E2_SMEM    (2 * E2_STAGE)        // 106496 -> 2 CTAs/SM (208 KB)

__device__ __forceinline__ void e2_issue(uint32_t st,
                                         const __half* __restrict__ Ahi, const __half* __restrict__ Alo,
                                         const __half* __restrict__ B,
                                         int ldA, int ldB, int kc, int tid) {
    const int col0 = kc * CHUNK_K;
#pragma unroll
    for (int i = 0; i < 8; i++) {        // A: 128 rows x 2 planes x 8 quads = 2048 ops
        int id = tid + 256 * i;
        int row = id >> 4, plane = (id >> 3) & 1, quad = id & 7;
        const __half* src = (plane ? Alo : Ahi) + (size_t)row * ldA + col0 + quad * 8;
        CP_ASYNC16(st + row * 272 + plane * 128 + quad * 16, src);
    }
#pragma unroll
    for (int i = 0; i < 4; i++) {        // B: 128 rows x 8 quads = 1024 ops
        int id = tid + 256 * i;
        int row = id >> 3, quad = id & 7;
        const __half* src = B + (size_t)row * ldB + col0 + quad * 8;
        CP_ASYNC16(st + E2_SMO_B + row * 144 + quad * 16, src);
    }
    asm volatile("cp.async.commit_group;" ::: "memory");
}

__device__ __forceinline__ void gemm2(const __half* __restrict__ Ahi, const __half* __restrict__ Alo,
                                      const __half* __restrict__ B,
                                      int ldA, int ldB, int nChunks,
                                      uint32_t sb, float (&acc)[2][8][4]) {
    const int tid  = threadIdx.x;
    const int wid  = tid >> 5;
    const int lane = tid & 31;
    const int wm   = (wid & 3) * 32;
    const int wn   = (wid >> 2) * 64;
    const int lrow = lane & 15;
    const int lkB  = (lane >> 4) * 16;   // byte offset within 32B k-slice

    e2_issue(sb, Ahi, Alo, B, ldA, ldB, 0, tid);

    for (int kc = 0; kc < nChunks; kc++) {
        asm volatile("cp.async.wait_group 0;" ::: "memory");
        __syncthreads();

        if (kc + 1 < nChunks)
            e2_issue(sb + ((kc + 1) & 1) * E2_STAGE, Ahi, Alo, B, ldA, ldB, kc + 1, tid);

        const uint32_t sA = sb + (kc & 1) * E2_STAGE;
        const uint32_t sB = sA + E2_SMO_B;
#pragma unroll
        for (int ks = 0; ks < 4; ks++) {
            uint32_t a[2][2][4];
#pragma unroll
            for (int mt = 0; mt < 2; mt++) {
                uint32_t ad = sA + (wm + mt * 16 + lrow) * 272 + ks * 32 + lkB;
                LDMX4(a[0][mt][0], a[0][mt][1], a[0][mt][2], a[0][mt][3], ad);
                LDMX4(a[1][mt][0], a[1][mt][1], a[1][mt][2], a[1][mt][3], ad + 128);
            }
            uint32_t b[4][4];
#pragma unroll
            for (int g = 0; g < 4; g++) {
                uint32_t bd = sB + (wn + g * 16 + lrow) * 144 + ks * 32 + lkB;
                LDMX4(b[g][0], b[g][1], b[g][2], b[g][3], bd);
            }
#pragma unroll
            for (int pa = 0; pa < 2; pa++)
#pragma unroll
                for (int mt = 0; mt < 2; mt++)
#pragma unroll
                    for (int g = 0; g < 4; g++) {
                        MMAF16(acc[mt][2 * g],
                               a[pa][mt][0], a[pa][mt][1], a[pa][mt][2], a[pa][mt][3],
                               b[g][0], b[g][2]);
                        MMAF16(acc[mt][2 * g + 1],
                               a[pa][mt][0], a[pa][mt][1], a[pa][mt][2], a[pa][mt][3],
                               b[g][1], b[g][3]);
                    }
        }
    }
    __syncthreads();
}

// =================================================================================
// Engine 1 (scores / PV): C = A . B^T, both single fp16 planes.
// Rows: 144B [128 data | 16 pad].
// =================================================================================
#define E1_SMO_B   18432                 // 128*144
#define E1_STAGE   36864
#define E1_SMEM    (2 * E1_STAGE)        // 73728 -> 2 CTAs/SM (144 KB)

__device__ __forceinline__ void e1_issue(uint32_t st,
                                         const __half* __restrict__ A,
                                         const __half* __restrict__ B,
                                         int ldA, int ldB, int kc, int tid) {
    const int col0 = kc * CHUNK_K;
#pragma unroll
    for (int i = 0; i < 4; i++) {
        int id = tid + 256 * i;
        int row = id >> 3, quad = id & 7;
        const __half* src = A + (size_t)row * ldA + col0 + quad * 8;
        CP_ASYNC16(st + row * 144 + quad * 16, src);
    }
#pragma unroll
    for (int i = 0; i < 4; i++) {
        int id = tid + 256 * i;
        int row = id >> 3, quad = id & 7;
        const __half* src = B + (size_t)row * ldB + col0 + quad * 8;
        CP_ASYNC16(st + E1_SMO_B + row * 144 + quad * 16, src);
    }
    asm volatile("cp.async.commit_group;" ::: "memory");
}

__device__ __forceinline__ void gemm1(const __half* __restrict__ A,
                                      const __half* __restrict__ B,
                                      int ldA, int ldB, int nChunks,
                                      uint32_t sb, float (&acc)[2][8][4]) {
    const int tid  = threadIdx.x;
    const int wid  = tid >> 5;
    const int lane = tid & 31;
    const int wm   = (wid & 3) * 32;
    const int wn   = (wid >> 2) * 64;
    const int lrow = lane & 15;
    const int lkB  = (lane >> 4) * 16;

    e1_issue(sb, A, B, ldA, ldB, 0, tid);

    for (int kc = 0; kc < nChunks; kc++) {
        asm volatile("cp.async.wait_group 0;" ::: "memory");
        __syncthreads();

        if (kc + 1 < nChunks)
            e1_issue(sb + ((kc + 1) & 1) * E1_STAGE, A, B, ldA, ldB, kc + 1, tid);

        const uint32_t sA = sb + (kc & 1) * E1_STAGE;
        const uint32_t sB = sA + E1_SMO_B;
#pragma unroll
        for (int ks = 0; ks < 4; ks++) {
            uint32_t a[2][4];
#pragma unroll
            for (int mt = 0; mt < 2; mt++) {
                uint32_t ad = sA + (wm + mt * 16 + lrow) * 144 + ks * 32 + lkB;
                LDMX4(a[mt][0], a[mt][1], a[mt][2], a[mt][3], ad);
            }
            uint32_t b[4][4];
#pragma unroll
            for (int g = 0; g < 4; g++) {
                uint32_t bd = sB + (wn + g * 16 + lrow) * 144 + ks * 32 + lkB;
                LDMX4(b[g][0], b[g][1], b[g][2], b[g][3], bd);
            }
#pragma unroll
            for (int mt = 0; mt < 2; mt++)
#pragma unroll
                for (int g = 0; g < 4; g++) {
                    MMAF16(acc[mt][2 * g],
                           a[mt][0], a[mt][1], a[mt][2], a[mt][3],
                           b[g][0], b[g][2]);
                    MMAF16(acc[mt][2 * g + 1],
                           a[mt][0], a[mt][1], a[mt][2], a[mt][3],
                           b[g][1], b[g][3]);
                }
        }
    }
    __syncthreads();
}

// =================================================================================
// GEMM kernels
// =================================================================================
#define TSTR 130   // transpose staging stride (halfs): odd word stride -> conflict-free 32-bit

__global__ void __launch_bounds__(256, 2) proj_tc(int mode) {
    extern __shared__ __align__(128) char smem[];
    float acc[2][8][4];
#pragma unroll
    for (int i = 0; i < 2; i++)
#pragma unroll
        for (int j = 0; j < 8; j++)
#pragma unroll
            for (int c = 0; c < 4; c++) acc[i][j][c] = 0.0f;

    const int m0 = blockIdx.y * 128;
    const int n0 = blockIdx.x * 128;
    gemm2(g_xh + (size_t)m0 * HID, g_xl + (size_t)m0 * HID,
          g_wf[mode] + (size_t)n0 * HID,
          HID, HID, HID / CHUNK_K, smem_u32(smem), acc);

    const int tid = threadIdx.x, wid = tid >> 5, lane = tid & 31;
    const int wm = (wid & 3) * 32, wn = (wid >> 2) * 64;
    const int g = lane >> 2, t2 = (lane & 3) * 2;

    if (mode != 2) {
        __half* dst = (mode == 0) ? g_qf : g_kf;
#pragma unroll
        for (int mt = 0; mt < 2; mt++)
#pragma unroll
            for (int ng = 0; ng < 8; ng++)
#pragma unroll
                for (int ci = 0; ci < 4; ci++) {
                    int m = m0 + wm + mt * 16 + g + ((ci >> 1) << 3);
                    int n = n0 + wn + ng * 8 + t2 + (ci & 1);
                    dst[(size_t)m * HID + n] = __float2half_rn(acc[mt][ng][ci]);
                }
    } else {
        // fused transpose: stage tile into smem as [n_local][m_local], then write v^T
        __half* ts = (__half*)smem;
#pragma unroll
        for (int mt = 0; mt < 2; mt++)
#pragma unroll
            for (int ng = 0; ng < 8; ng++)
#pragma unroll
                for (int ci = 0; ci < 4; ci++) {
                    int ml = wm + mt * 16 + g + ((ci >> 1) << 3);
                    int nl = wn + ng * 8 + t2 + (ci & 1);
                    ts[nl * TSTR + ml] = __float2half_rn(acc[mt][ng][ci]);
                }
        __syncthreads();
        const int b  = m0 >> 12;            // batch of this m-tile
        const int s0 = m0 & (SLEN - 1);     // seq offset within batch
        const int r    = tid & 127;         // h row within tile
        const int part = tid >> 7;          // 0/1 -> 64-half halves
        __half* drow = g_vt + ((size_t)b * HID + n0 + r) * SLEN + s0 + part * 64;
        const __half* srow = ts + r * TSTR + part * 64;
        // shared side: scalar 32-bit loads (4B aligned); global side: 16B stores
#pragma unroll
        for (int k = 0; k < 8; k++) {
            uint32_t v0, v1, v2, v3;
            uint32_t ad = smem_u32(srow + k * 8);
            asm volatile("ld.shared.b32 %0, [%1];"      : "=r"(v0) : "r"(ad));
            asm volatile("ld.shared.b32 %0, [%1+4];"    : "=r"(v1) : "r"(ad));
            asm volatile("ld.shared.b32 %0, [%1+8];"    : "=r"(v2) : "r"(ad));
            asm volatile("ld.shared.b32 %0, [%1+12];"   : "=r"(v3) : "r"(ad));
            *(uint4*)(drow + k * 8) = make_uint4(v0, v1, v2, v3);
        }
    }
}

__global__ void __launch_bounds__(256, 2) scores_tc() {
    const int m0 = blockIdx.y * 128;
    const int n0 = blockIdx.x * 128;
    if (n0 > m0 + 127) return;                 // fully masked tile
    const int b = blockIdx.z;

    extern __shared__ __align__(128) char smem[];
    float acc[2][8][4];
#pragma unroll
    for (int i = 0; i < 2; i++)
#pragma unroll
        for (int j = 0; j < 8; j++)
#pragma unroll
            for (int c = 0; c < 4; c++) acc[i][j][c] = 0.0f;

    gemm1(g_qf + (size_t)(b * SLEN + m0) * HID,
          g_kf + (size_t)(b * SLEN + n0) * HID,
          HID, HID, HID / CHUNK_K, smem_u32(smem), acc);

    const float scale = 0.03125f;   // 1/sqrt(1024)
    const int tid = threadIdx.x, wid = tid >> 5, lane = tid & 31;
    const int wm = (wid & 3) * 32, wn = (wid >> 2) * 64;
    const int g = lane >> 2, t2 = (lane & 3) * 2;
#pragma unroll
    for (int mt = 0; mt < 2; mt++)
#pragma unroll
        for (int ng = 0; ng < 8; ng++)
#pragma unroll
            for (int ci2 = 0; ci2 < 2; ci2++) {
                int m = m0 + wm + mt * 16 + g + ci2 * 8;
                int n = n0 + wn + ng * 8 + t2;
                __half2 h = __floats2half2_rn(acc[mt][ng][2 * ci2] * scale,
                                              acc[mt][ng][2 * ci2 + 1] * scale);
                *(__half2*)(g_Sh + ((size_t)b * SLEN + m) * SLEN + n) = h;
            }
}

__global__ void __launch_bounds__(256, 2) pv_tc(float* __restrict__ out) {
    extern __shared__ __align__(128) char smem[];
    float acc[2][8][4];
#pragma unroll
    for (int i = 0; i < 2; i++)
#pragma unroll
        for (int j = 0; j < 8; j++)
#pragma unroll
            for (int c = 0; c < 4; c++) acc[i][j][c] = 0.0f;

    const int n0 = blockIdx.x * 128;
    const int m0 = (int)(gridDim.y - 1 - blockIdx.y) * 128;   // heavy tiles first
    const int b  = blockIdx.z;
    const int nc = (m0 + 128) / CHUNK_K;

    gemm1(g_pf + (size_t)(b * SLEN + m0) * SLEN,
          g_vt + (size_t)(b * HID + n0) * SLEN,
          SLEN, SLEN, nc, smem_u32(smem), acc);

    const int tid = threadIdx.x, wid = tid >> 5, lane = tid & 31;
    const int wm = (wid & 3) * 32, wn = (wid >> 2) * 64;
    const int g = lane >> 2, t2 = (lane & 3) * 2;
#pragma unroll
    for (int mt = 0; mt < 2; mt++)
#pragma unroll
        for (int ng = 0; ng < 8; ng++)
#pragma unroll
            for (int ci2 = 0; ci2 < 2; ci2++) {
                int m = m0 + wm + mt * 16 + g + ci2 * 8;
                int n = n0 + wn + ng * 8 + t2;
                float2 v = make_float2(acc[mt][ng][2 * ci2], acc[mt][ng][2 * ci2 + 1]);
                *(float2*)(out + ((size_t)b * SLEN + m) * HID + n) = v;
            }
}

// ---------------- softmax: Sh (scaled fp16) -> p fp16, single global pass ----------------
__global__ void __launch_bounds__(256) softmax_kernel() {
    __shared__ float red[16];
    const int row = blockIdx.x;
    const int i   = row & (SLEN - 1);
    const int tid = threadIdx.x, wid = tid >> 5, lane = tid & 31;
    const int n    = i + 1;
    const int jpad = ((i >> 7) + 1) << 7;
    const __half2* srow2 = (const __half2*)(g_Sh + (size_t)row * SLEN);

    float2 v[8];
    float lm = -3.0e38f;
#pragma unroll
    for (int it = 0; it < 8; it++) {
        int j2 = tid + 256 * it;
        int j  = 2 * j2;
        if (j < n) {
            float2 f = __half22float2(srow2[j2]);
            if (j + 1 >= n) f.y = -3.0e38f;
            v[it] = f;
            lm = fmaxf(lm, fmaxf(f.x, f.y));
        } else {
            v[it] = make_float2(-3.0e38f, -3.0e38f);
        }
    }
#pragma unroll
    for (int o = 16; o; o >>= 1) lm = fmaxf(lm, __shfl_xor_sync(0xffffffffu, lm, o));
    if (lane == 0) red[wid] = lm;
    __syncthreads();
    if (tid == 0) {
        float m = red[0];
#pragma unroll
        for (int w = 1; w < 8; w++) m = fmaxf(m, red[w]);
        red[0] = m;
    }
    __syncthreads();
    const float mx = red[0];

    float ls = 0.0f;
#pragma unroll
    for (int it = 0; it < 8; it++) {
        float ex = (v[it].x > -1.0e38f) ? __expf(v[it].x - mx) : 0.0f;
        float ey = (v[it].y > -1.0e38f) ? __expf(v[it].y - mx) : 0.0f;
        v[it].x = ex; v[it].y = ey;
        ls += ex + ey;
    }
#pragma unroll
    for (int o = 16; o; o >>= 1) ls += __shfl_xor_sync(0xffffffffu, ls, o);
    if (lane == 0) red[8 + wid] = ls;
    __syncthreads();
    if (tid == 0) {
        float s = 0.0f;
#pragma unroll
        for (int w = 0; w < 8; w++) s += red[8 + w];
        red[8] = 1.0f / s;
    }
    __syncthreads();
    const float inv = red[8];

    __half2* pf2 = (__half2*)(g_pf + (size_t)row * SLEN);
#pragma unroll
    for (int it = 0; it < 8; it++) {
        int j2 = tid + 256 * it;
        if (2 * j2 < jpad)
            pf2[j2] = __floats2half2_rn(v[it].x * inv, v[it].y * inv);
    }
}

// ---------------- input conversions ----------------
__global__ void __launch_bounds__(256) split_x(const float* __restrict__ x) {
    size_t idx = (size_t)blockIdx.x * 256 + threadIdx.x;
    float v = x[idx];
    __half hi = __float2half_rn(v);
    g_xh[idx] = hi;
    g_xl[idx] = __float2half_rn(v - __half2float(hi));
}

__global__ void __launch_bounds__(256) conv_w(const float* __restrict__ W, int which) {
    size_t idx = (size_t)blockIdx.x * 256 + threadIdx.x;
    g_wf[which][idx] = __float2half_rn(W[idx]);
}

// =================================================================================
// Launch (launch index 5 = scores_tc: profiled by ncu -s 5 -c 1)
// =================================================================================
extern "C" void kernel_launch(void* const* d_in, const int* in_sizes, int n_in,
                              void* d_out, int out_size) {
    (void)in_sizes; (void)n_in; (void)out_size;
    const float* x  = (const float*)d_in[0];
    const float* Wq = (const float*)d_in[1];
    const float* Wk = (const float*)d_in[2];
    const float* Wv = (const float*)d_in[3];
    float* out = (float*)d_out;

    static bool attr_set = false;
    if (!attr_set) {
        cudaFuncSetAttribute(proj_tc,   cudaFuncAttributeMaxDynamicSharedMemorySize, E2_SMEM);
        cudaFuncSetAttribute(scores_tc, cudaFuncAttributeMaxDynamicSharedMemorySize, E1_SMEM);
        cudaFuncSetAttribute(pv_tc,     cudaFuncAttributeMaxDynamicSharedMemorySize, E1_SMEM);
        attr_set = true;
    }

    dim3 pgrid(HID / 128, MTOT / 128);                 // (8, 128)

    split_x<<<(MTOT * HID) / 256, 256>>>(x);           // 0
    conv_w<<<(HID * HID) / 256, 256>>>(Wq, 0);         // 1
    conv_w<<<(HID * HID) / 256, 256>>>(Wk, 1);         // 2
    proj_tc<<<pgrid, 256, E2_SMEM>>>(0);               // 3  -> q
    proj_tc<<<pgrid, 256, E2_SMEM>>>(1);               // 4  -> k
    scores_tc<<<dim3(SLEN / 128, SLEN / 128, BATCH), 256, E1_SMEM>>>();   // 5 (profiled)
    conv_w<<<(HID * HID) / 256, 256>>>(Wv, 2);         // 6
    proj_tc<<<pgrid, 256, E2_SMEM>>>(2);               // 7  -> v^T (fused transpose)
    softmax_kernel<<<MTOT, 256>>>();                   // 8
    pv_tc<<<dim3(HID / 128, SLEN / 128, BATCH), 256, E1_SMEM>>>(out);     // 9
}

// round 13
// speedup vs baseline: 1.6747x; 1.6747x over previous
#include <cuda_runtime.h>
#include <cuda_fp16.h>
#include <cstdint>

#define BATCH 4
#define SLEN  4096
#define HID   1024
#define MTOT  (BATCH * SLEN)   // 16384

// ---------------- static scratch (no runtime allocation) ----------------
__device__ __align__(16) __half g_xh[(size_t)MTOT * HID];
__device__ __align__(16) __half g_xl[(size_t)MTOT * HID];
__device__ __align__(16) __half g_wf[3][(size_t)HID * HID];  // Wq,Wk,Wv fp16 planes
__device__ __align__(16) __half g_qf[(size_t)MTOT * HID];    // q fp16 plane
__device__ __align__(16) __half g_kf[(size_t)MTOT * HID];    // k fp16 plane
__device__ __align__(16) __half g_vt[(size_t)MTOT * HID];    // v^T [b][h][s]
__device__ __align__(16) __half g_pf[(size_t)MTOT * SLEN];   // p fp16, zero-padded
__device__ __align__(16) __half g_Sh[(size_t)BATCH * SLEN * SLEN];  // scaled scores fp16

// ---------------- common helpers ----------------
__device__ __forceinline__ uint32_t smem_u32(const void* p) {
    return (uint32_t)__cvta_generic_to_shared(p);
}
#define CP_ASYNC16(dst, src) \
    asm volatile("cp.async.cg.shared.global [%0], [%1], 16;" :: "r"(dst), "l"(src) : "memory")
#define LDMX4(R0, R1, R2, R3, addr)                                              \
    asm volatile("ldmatrix.sync.aligned.m8n8.x4.shared.b16 {%0,%1,%2,%3}, [%4];" \
                 : "=r"(R0), "=r"(R1), "=r"(R2), "=r"(R3) : "r"(addr))
#define MMAF16(C, A0, A1, A2, A3, B0, B1)                                      \
    asm volatile("mma.sync.aligned.m16n8k16.row.col.f32.f16.f16.f32 "          \
                 "{%0,%1,%2,%3}, {%4,%5,%6,%7}, {%8,%9}, {%0,%1,%2,%3};"       \
                 : "+f"(C[0]), "+f"(C[1]), "+f"(C[2]), "+f"(C[3])              \
                 : "r"(A0), "r"(A1), "r"(A2), "r"(A3), "r"(B0), "r"(B1))

#define CHUNK_K 32   // reverted: 64 regressed (LDSM bank phases + issue bursts)

// =================================================================================
// Engine 2 (q projection): C = (A_hi + A_lo) . B^T, B single fp16 plane.
// 256 thr, warps 4m x 2n (warp tile 32x64), 2-stage, occ 2.
// =================================================================================
#define E2_SMO_B   18432
#define E2_STAGE   28672
#define E2_SMEM    (2 * E2_STAGE)        // 57344

__device__ __forceinline__ void e2_issue(uint32_t st,
                                         const __half* __restrict__ Ahi, const __half* __restrict__ Alo,
                                         const __half* __restrict__ B,
                                         int ldA, int ldB, int kc, int tid) {
    const int col0 = kc * CHUNK_K;
#pragma unroll
    for (int i = 0; i < 4; i++) {
        int id = tid + 256 * i;
        int row = id >> 3, plane = (id >> 2) & 1, quad = id & 3;
        const __half* src = (plane ? Alo : Ahi) + (size_t)row * ldA + col0 + quad * 8;
        CP_ASYNC16(st + row * 144 + plane * 64 + quad * 16, src);
    }
#pragma unroll
    for (int i = 0; i < 2; i++) {
        int id = tid + 256 * i;
        int row = id >> 2, quad = id & 3;
        const __half* src = B + (size_t)row * ldB + col0 + quad * 8;
        CP_ASYNC16(st + E2_SMO_B + row * 80 + quad * 16, src);
    }
    asm volatile("cp.async.commit_group;" ::: "memory");
}

__device__ __forceinline__ void gemm2(const __half* __restrict__ Ahi, const __half* __restrict__ Alo,
                                      const __half* __restrict__ B,
                                      int ldA, int ldB, int nChunks,
                                      uint32_t sb, float (&acc)[2][8][4]) {
    const int tid  = threadIdx.x;
    const int wid  = tid >> 5;
    const int lane = tid & 31;
    const int wm   = (wid & 3) * 32;
    const int wn   = (wid >> 2) * 64;
    const int lrow = lane & 15;
    const int lkB  = (lane >> 4) * 8;

    e2_issue(sb, Ahi, Alo, B, ldA, ldB, 0, tid);

    for (int kc = 0; kc < nChunks; kc++) {
        asm volatile("cp.async.wait_group 0;" ::: "memory");
        __syncthreads();

        if (kc + 1 < nChunks)
            e2_issue(sb + ((kc + 1) & 1) * E2_STAGE, Ahi, Alo, B, ldA, ldB, kc + 1, tid);

        const uint32_t sA = sb + (kc & 1) * E2_STAGE;
        const uint32_t sB = sA + E2_SMO_B;
#pragma unroll
        for (int ks = 0; ks < 2; ks++) {
            uint32_t a[2][2][4];
#pragma unroll
            for (int mt = 0; mt < 2; mt++) {
                uint32_t ad = sA + ((wm + mt * 16 + lrow) * 72 + ks * 16 + lkB) * 2;
                LDMX4(a[0][mt][0], a[0][mt][1], a[0][mt][2], a[0][mt][3], ad);
                LDMX4(a[1][mt][0], a[1][mt][1], a[1][mt][2], a[1][mt][3], ad + 64);
            }
            uint32_t b[4][4];
#pragma unroll
            for (int g = 0; g < 4; g++) {
                uint32_t bd = sB + (wn + g * 16 + lrow) * 80 + (ks * 16 + lkB) * 2;
                LDMX4(b[g][0], b[g][1], b[g][2], b[g][3], bd);
            }
#pragma unroll
            for (int pa = 0; pa < 2; pa++)
#pragma unroll
                for (int mt = 0; mt < 2; mt++)
#pragma unroll
                    for (int g = 0; g < 4; g++) {
                        MMAF16(acc[mt][2 * g],
                               a[pa][mt][0], a[pa][mt][1], a[pa][mt][2], a[pa][mt][3],
                               b[g][0], b[g][2]);
                        MMAF16(acc[mt][2 * g + 1],
                               a[pa][mt][0], a[pa][mt][1], a[pa][mt][2], a[pa][mt][3],
                               b[g][1], b[g][3]);
                    }
        }
    }
    __syncthreads();
}

// =================================================================================
// Engine 1 (k/v projections, scores, PV): C = A . B^T, both single fp16 planes.
// =================================================================================
#define E1_SMO_B   10240
#define E1_STAGE   20480
#define E1_SMEM    (2 * E1_STAGE)        // 40960

__device__ __forceinline__ void e1_issue(uint32_t st,
                                         const __half* __restrict__ A,
                                         const __half* __restrict__ B,
                                         int ldA, int ldB, int kc, int tid) {
    const int col0 = kc * CHUNK_K;
#pragma unroll
    for (int i = 0; i < 2; i++) {
        int id = tid + 256 * i;
        int row = id >> 2, quad = id & 3;
        const __half* src = A + (size_t)row * ldA + col0 + quad * 8;
        CP_ASYNC16(st + row * 80 + quad * 16, src);
    }
#pragma unroll
    for (int i = 0; i < 2; i++) {
        int id = tid + 256 * i;
        int row = id >> 2, quad = id & 3;
        const __half* src = B + (size_t)row * ldB + col0 + quad * 8;
        CP_ASYNC16(st + E1_SMO_B + row * 80 + quad * 16, src);
    }
    asm volatile("cp.async.commit_group;" ::: "memory");
}

__device__ __forceinline__ void gemm1(const __half* __restrict__ A,
                                      const __half* __restrict__ B,
                                      int ldA, int ldB, int nChunks,
                                      uint32_t sb, float (&acc)[2][8][4]) {
    const int tid  = threadIdx.x;
    const int wid  = tid >> 5;
    const int lane = tid & 31;
    const int wm   = (wid & 3) * 32;
    const int wn   = (wid >> 2) * 64;
    const int lrow = lane & 15;
    const int lkB  = (lane >> 4) * 8;

    e1_issue(sb, A, B, ldA, ldB, 0, tid);

    for (int kc = 0; kc < nChunks; kc++) {
        asm volatile("cp.async.wait_group 0;" ::: "memory");
        __syncthreads();

        if (kc + 1 < nChunks)
            e1_issue(sb + ((kc + 1) & 1) * E1_STAGE, A, B, ldA, ldB, kc + 1, tid);

        const uint32_t sA = sb + (kc & 1) * E1_STAGE;
        const uint32_t sB = sA + E1_SMO_B;
#pragma unroll
        for (int ks = 0; ks < 2; ks++) {
            uint32_t a[2][4];
#pragma unroll
            for (int mt = 0; mt < 2; mt++) {
                uint32_t ad = sA + (wm + mt * 16 + lrow) * 80 + (ks * 16 + lkB) * 2;
                LDMX4(a[mt][0], a[mt][1], a[mt][2], a[mt][3], ad);
            }
            uint32_t b[4][4];
#pragma unroll
            for (int g = 0; g < 4; g++) {
                uint32_t bd = sB + (wn + g * 16 + lrow) * 80 + (ks * 16 + lkB) * 2;
                LDMX4(b[g][0], b[g][1], b[g][2], b[g][3], bd);
            }
#pragma unroll
            for (int mt = 0; mt < 2; mt++)
#pragma unroll
                for (int g = 0; g < 4; g++) {
                    MMAF16(acc[mt][2 * g],
                           a[mt][0], a[mt][1], a[mt][2], a[mt][3],
                           b[g][0], b[g][2]);
                    MMAF16(acc[mt][2 * g + 1],
                           a[mt][0], a[mt][1], a[mt][2], a[mt][3],
                           b[g][1], b[g][3]);
                }
        }
    }
    __syncthreads();
}

// =================================================================================
// GEMM kernels
// =================================================================================
#define TSTR 130   // transpose staging stride (halfs): odd word stride -> conflict-free 32-bit

__global__ void __launch_bounds__(256, 2) proj_tc(int mode) {
    extern __shared__ __align__(128) char smem[];
    float acc[2][8][4];
#pragma unroll
    for (int i = 0; i < 2; i++)
#pragma unroll
        for (int j = 0; j < 8; j++)
#pragma unroll
            for (int c = 0; c < 4; c++) acc[i][j][c] = 0.0f;

    const int m0 = blockIdx.y * 128;
    const int n0 = blockIdx.x * 128;
    if (mode == 0) {
        // q: 2-term (x_hi + x_lo) . W  — exact x
        gemm2(g_xh + (size_t)m0 * HID, g_xl + (size_t)m0 * HID,
              g_wf[0] + (size_t)n0 * HID,
              HID, HID, HID / CHUNK_K, smem_u32(smem), acc);
    } else {
        // k/v: 1-term fp16(x) . W  — output rounded to fp16 anyway
        gemm1(g_xh + (size_t)m0 * HID,
              g_wf[mode] + (size_t)n0 * HID,
              HID, HID, HID / CHUNK_K, smem_u32(smem), acc);
    }

    const int tid = threadIdx.x, wid = tid >> 5, lane = tid & 31;
    const int wm = (wid & 3) * 32, wn = (wid >> 2) * 64;
    const int g = lane >> 2, t2 = (lane & 3) * 2;

    if (mode != 2) {
        __half* dst = (mode == 0) ? g_qf : g_kf;
#pragma unroll
        for (int mt = 0; mt < 2; mt++)
#pragma unroll
            for (int ng = 0; ng < 8; ng++)
#pragma unroll
                for (int ci = 0; ci < 4; ci++) {
                    int m = m0 + wm + mt * 16 + g + ((ci >> 1) << 3);
                    int n = n0 + wn + ng * 8 + t2 + (ci & 1);
                    dst[(size_t)m * HID + n] = __float2half_rn(acc[mt][ng][ci]);
                }
    } else {
        // fused transpose: stage tile into smem as [n_local][m_local], then write v^T
        __half* ts = (__half*)smem;
#pragma unroll
        for (int mt = 0; mt < 2; mt++)
#pragma unroll
            for (int ng = 0; ng < 8; ng++)
#pragma unroll
                for (int ci = 0; ci < 4; ci++) {
                    int ml = wm + mt * 16 + g + ((ci >> 1) << 3);
                    int nl = wn + ng * 8 + t2 + (ci & 1);
                    ts[nl * TSTR + ml] = __float2half_rn(acc[mt][ng][ci]);
                }
        __syncthreads();
        const int b  = m0 >> 12;            // batch of this m-tile
        const int s0 = m0 & (SLEN - 1);     // seq offset within batch
        const int r    = tid & 127;         // h row within tile
        const int part = tid >> 7;          // 0/1 -> 64-half halves
        __half* drow = g_vt + ((size_t)b * HID + n0 + r) * SLEN + s0 + part * 64;
        const __half* srow = ts + r * TSTR + part * 64;
        // shared side: scalar 32-bit loads (4B aligned); global side: 16B stores
#pragma unroll
        for (int k = 0; k < 8; k++) {
            uint32_t v0, v1, v2, v3;
            uint32_t ad = smem_u32(srow + k * 8);
            asm volatile("ld.shared.b32 %0, [%1];"      : "=r"(v0) : "r"(ad));
            asm volatile("ld.shared.b32 %0, [%1+4];"    : "=r"(v1) : "r"(ad));
            asm volatile("ld.shared.b32 %0, [%1+8];"    : "=r"(v2) : "r"(ad));
            asm volatile("ld.shared.b32 %0, [%1+12];"   : "=r"(v3) : "r"(ad));
            *(uint4*)(drow + k * 8) = make_uint4(v0, v1, v2, v3);
        }
    }
}

__global__ void __launch_bounds__(256, 2) scores_tc() {
    const int m0 = blockIdx.y * 128;
    const int n0 = blockIdx.x * 128;
    if (n0 > m0 + 127) return;                 // fully masked tile
    const int b = blockIdx.z;

    extern __shared__ __align__(128) char smem[];
    float acc[2][8][4];
#pragma unroll
    for (int i = 0; i < 2; i++)
#pragma unroll
        for (int j = 0; j < 8; j++)
#pragma unroll
            for (int c = 0; c < 4; c++) acc[i][j][c] = 0.0f;

    gemm1(g_qf + (size_t)(b * SLEN + m0) * HID,
          g_kf + (size_t)(b * SLEN + n0) * HID,
          HID, HID, HID / CHUNK_K, smem_u32(smem), acc);

    const float scale = 0.03125f;   // 1/sqrt(1024)
    const int tid = threadIdx.x, wid = tid >> 5, lane = tid & 31;
    const int wm = (wid & 3) * 32, wn = (wid >> 2) * 64;
    const int g = lane >> 2, t2 = (lane & 3) * 2;
#pragma unroll
    for (int mt = 0; mt < 2; mt++)
#pragma unroll
        for (int ng = 0; ng < 8; ng++)
#pragma unroll
            for (int ci2 = 0; ci2 < 2; ci2++) {
                int m = m0 + wm + mt * 16 + g + ci2 * 8;
                int n = n0 + wn + ng * 8 + t2;
                __half2 h = __floats2half2_rn(acc[mt][ng][2 * ci2] * scale,
                                              acc[mt][ng][2 * ci2 + 1] * scale);
                *(__half2*)(g_Sh + ((size_t)b * SLEN + m) * SLEN + n) = h;
            }
}

__global__ void __launch_bounds__(256, 2) pv_tc(float* __restrict__ out) {
    extern __shared__ __align__(128) char smem[];
    float acc[2][8][4];
#pragma unroll
    for (int i = 0; i < 2; i++)
#pragma unroll
        for (int j = 0; j < 8; j++)
#pragma unroll
            for (int c = 0; c < 4; c++) acc[i][j][c] = 0.0f;

    const int n0 = blockIdx.x * 128;
    const int m0 = (int)(gridDim.y - 1 - blockIdx.y) * 128;   // heavy tiles first
    const int b  = blockIdx.z;
    const int nc = (m0 + 128) / CHUNK_K;

    gemm1(g_pf + (size_t)(b * SLEN + m0) * SLEN,
          g_vt + (size_t)(b * HID + n0) * SLEN,
          SLEN, SLEN, nc, smem_u32(smem), acc);

    const int tid = threadIdx.x, wid = tid >> 5, lane = tid & 31;
    const int wm = (wid & 3) * 32, wn = (wid >> 2) * 64;
    const int g = lane >> 2, t2 = (lane & 3) * 2;
#pragma unroll
    for (int mt = 0; mt < 2; mt++)
#pragma unroll
        for (int ng = 0; ng < 8; ng++)
#pragma unroll
            for (int ci2 = 0; ci2 < 2; ci2++) {
                int m = m0 + wm + mt * 16 + g + ci2 * 8;
                int n = n0 + wn + ng * 8 + t2;
                float2 v = make_float2(acc[mt][ng][2 * ci2], acc[mt][ng][2 * ci2 + 1]);
                *(float2*)(out + ((size_t)b * SLEN + m) * HID + n) = v;
            }
}

// ---------------- softmax: Sh (scaled fp16) -> p fp16, single global pass ----------------
__global__ void __launch_bounds__(256) softmax_kernel() {
    __shared__ float red[16];
    const int row = blockIdx.x;
    const int i   = row & (SLEN - 1);
    const int tid = threadIdx.x, wid = tid >> 5, lane = tid & 31;
    const int n    = i + 1;
    const int jpad = ((i >> 7) + 1) << 7;
    const __half2* srow2 = (const __half2*)(g_Sh + (size_t)row * SLEN);

    float2 v[8];
    float lm = -3.0e38f;
#pragma unroll
    for (int it = 0; it < 8; it++) {
        int j2 = tid + 256 * it;
        int j  = 2 * j2;
        if (j < n) {
            float2 f = __half22float2(srow2[j2]);
            if (j + 1 >= n) f.y = -3.0e38f;
            v[it] = f;
            lm = fmaxf(lm, fmaxf(f.x, f.y));
        } else {
            v[it] = make_float2(-3.0e38f, -3.0e38f);
        }
    }
#pragma unroll
    for (int o = 16; o; o >>= 1) lm = fmaxf(lm, __shfl_xor_sync(0xffffffffu, lm, o));
    if (lane == 0) red[wid] = lm;
    __syncthreads();
    if (tid == 0) {
        float m = red[0];
#pragma unroll
        for (int w = 1; w < 8; w++) m = fmaxf(m, red[w]);
        red[0] = m;
    }
    __syncthreads();
    const float mx = red[0];

    float ls = 0.0f;
#pragma unroll
    for (int it = 0; it < 8; it++) {
        float ex = (v[it].x > -1.0e38f) ? __expf(v[it].x - mx) : 0.0f;
        float ey = (v[it].y > -1.0e38f) ? __expf(v[it].y - mx) : 0.0f;
        v[it].x = ex; v[it].y = ey;
        ls += ex + ey;
    }
#pragma unroll
    for (int o = 16; o; o >>= 1) ls += __shfl_xor_sync(0xffffffffu, ls, o);
    if (lane == 0) red[8 + wid] = ls;
    __syncthreads();
    if (tid == 0) {
        float s = 0.0f;
#pragma unroll
        for (int w = 0; w < 8; w++) s += red[8 + w];
        red[8] = 1.0f / s;
    }
    __syncthreads();
    const float inv = red[8];

    __half2* pf2 = (__half2*)(g_pf + (size_t)row * SLEN);
#pragma unroll
    for (int it = 0; it < 8; it++) {
        int j2 = tid + 256 * it;
        if (2 * j2 < jpad)
            pf2[j2] = __floats2half2_rn(v[it].x * inv, v[it].y * inv);
    }
}

// ---------------- input conversions ----------------
__global__ void __launch_bounds__(256) split_x(const float* __restrict__ x) {
    size_t idx = (size_t)blockIdx.x * 256 + threadIdx.x;
    float v = x[idx];
    __half hi = __float2half_rn(v);
    g_xh[idx] = hi;
    g_xl[idx] = __float2half_rn(v - __half2float(hi));
}

__global__ void __launch_bounds__(256) conv_w(const float* __restrict__ W, int which) {
    size_t idx = (size_t)blockIdx.x * 256 + threadIdx.x;
    g_wf[which][idx] = __float2half_rn(W[idx]);
}

// =================================================================================
// Launch (launch index 5 = scores_tc: profiled by ncu -s 5 -c 1)
// =================================================================================
extern "C" void kernel_launch(void* const* d_in, const int* in_sizes, int n_in,
                              void* d_out, int out_size) {
    (void)in_sizes; (void)n_in; (void)out_size;
    const float* x  = (const float*)d_in[0];
    const float* Wq = (const float*)d_in[1];
    const float* Wk = (const float*)d_in[2];
    const float* Wv = (const float*)d_in[3];
    float* out = (float*)d_out;

    static bool attr_set = false;
    if (!attr_set) {
        cudaFuncSetAttribute(proj_tc,   cudaFuncAttributeMaxDynamicSharedMemorySize, E2_SMEM);
        cudaFuncSetAttribute(scores_tc, cudaFuncAttributeMaxDynamicSharedMemorySize, E1_SMEM);
        cudaFuncSetAttribute(pv_tc,     cudaFuncAttributeMaxDynamicSharedMemorySize, E1_SMEM);
        attr_set = true;
    }

    dim3 pgrid(HID / 128, MTOT / 128);                 // (8, 128)

    split_x<<<(MTOT * HID) / 256, 256>>>(x);           // 0
    conv_w<<<(HID * HID) / 256, 256>>>(Wq, 0);         // 1
    conv_w<<<(HID * HID) / 256, 256>>>(Wk, 1);         // 2
    proj_tc<<<pgrid, 256, E2_SMEM>>>(0);               // 3  -> q (2-term)
    proj_tc<<<pgrid, 256, E1_SMEM>>>(1);               // 4  -> k (1-term)
    scores_tc<<<dim3(SLEN / 128, SLEN / 128, BATCH), 256, E1_SMEM>>>();   // 5 (profiled)
    conv_w<<<(HID * HID) / 256, 256>>>(Wv, 2);         // 6
    proj_tc<<<pgrid, 256, E2_SMEM>>>(2);               // 7  -> v^T (1-term + fused transpose)
    softmax_kernel<<<MTOT, 256>>>();                   // 8
    pv_tc<<<dim3(HID / 128, SLEN / 128, BATCH), 256, E1_SMEM>>>(out);     // 9
}

// round 15
// speedup vs baseline: 1.8925x; 1.1301x over previous
#include <cuda_runtime.h>
#include <cuda_fp16.h>
#include <cstdint>

#define BATCH 4
#define SLEN  4096
#define HID   1024
#define MTOT  (BATCH * SLEN)   // 16384

// ---------------- static scratch (no runtime allocation) ----------------
__device__ __align__(16) __half g_xf[(size_t)MTOT * HID];    // x fp16 plane
__device__ __align__(16) __half g_wf[3][(size_t)HID * HID];  // Wq,Wk,Wv fp16 planes
__device__ __align__(16) __half g_qf[(size_t)MTOT * HID];    // q fp16 plane
__device__ __align__(16) __half g_kf[(size_t)MTOT * HID];    // k fp16 plane
__device__ __align__(16) __half g_vt[(size_t)MTOT * HID];    // v^T [b][h][s]
__device__ __align__(16) __half g_pf[(size_t)MTOT * SLEN];   // p fp16, zero-padded
__device__ __align__(16) __half g_Sh[(size_t)BATCH * SLEN * SLEN];  // scaled scores fp16

// ---------------- common helpers ----------------
__device__ __forceinline__ uint32_t smem_u32(const void* p) {
    return (uint32_t)__cvta_generic_to_shared(p);
}
#define CP_ASYNC16(dst, src) \
    asm volatile("cp.async.cg.shared.global [%0], [%1], 16;" :: "r"(dst), "l"(src) : "memory")
#define LDMX4(R0, R1, R2, R3, addr)                                              \
    asm volatile("ldmatrix.sync.aligned.m8n8.x4.shared.b16 {%0,%1,%2,%3}, [%4];" \
                 : "=r"(R0), "=r"(R1), "=r"(R2), "=r"(R3) : "r"(addr))
#define MMAF16(C, A0, A1, A2, A3, B0, B1)                                      \
    asm volatile("mma.sync.aligned.m16n8k16.row.col.f32.f16.f16.f32 "          \
                 "{%0,%1,%2,%3}, {%4,%5,%6,%7}, {%8,%9}, {%0,%1,%2,%3};"       \
                 : "+f"(C[0]), "+f"(C[1]), "+f"(C[2]), "+f"(C[3])              \
                 : "r"(A0), "r"(A1), "r"(A2), "r"(A3), "r"(B0), "r"(B1))

#define CHUNK_K 32

// =================================================================================
// Engine 1 (all GEMMs): C = A . B^T, both single fp16 planes.
// 256 thr, warps 4m x 2n (warp tile 32x64), 2-stage, occ 2.
// Rows: 80B [64B data | 16B pad].
// =================================================================================
#define E1_SMO_B   10240
#define E1_STAGE   20480
#define E1_SMEM    (2 * E1_STAGE)        // 40960

__device__ __forceinline__ void e1_issue(uint32_t st,
                                         const __half* __restrict__ A,
                                         const __half* __restrict__ B,
                                         int ldA, int ldB, int kc, int tid) {
    const int col0 = kc * CHUNK_K;
#pragma unroll
    for (int i = 0; i < 2; i++) {
        int id = tid + 256 * i;
        int row = id >> 2, quad = id & 3;
        const __half* src = A + (size_t)row * ldA + col0 + quad * 8;
        CP_ASYNC16(st + row * 80 + quad * 16, src);
    }
#pragma unroll
    for (int i = 0; i < 2; i++) {
        int id = tid + 256 * i;
        int row = id >> 2, quad = id & 3;
        const __half* src = B + (size_t)row * ldB + col0 + quad * 8;
        CP_ASYNC16(st + E1_SMO_B + row * 80 + quad * 16, src);
    }
    asm volatile("cp.async.commit_group;" ::: "memory");
}

__device__ __forceinline__ void gemm1(const __half* __restrict__ A,
                                      const __half* __restrict__ B,
                                      int ldA, int ldB, int nChunks,
                                      uint32_t sb, float (&acc)[2][8][4]) {
    const int tid  = threadIdx.x;
    const int wid  = tid >> 5;
    const int lane = tid & 31;
    const int wm   = (wid & 3) * 32;
    const int wn   = (wid >> 2) * 64;
    const int lrow = lane & 15;
    const int lkB  = (lane >> 4) * 8;

    e1_issue(sb, A, B, ldA, ldB, 0, tid);

    for (int kc = 0; kc < nChunks; kc++) {
        asm volatile("cp.async.wait_group 0;" ::: "memory");
        __syncthreads();

        if (kc + 1 < nChunks)
            e1_issue(sb + ((kc + 1) & 1) * E1_STAGE, A, B, ldA, ldB, kc + 1, tid);

        const uint32_t sA = sb + (kc & 1) * E1_STAGE;
        const uint32_t sB = sA + E1_SMO_B;
#pragma unroll
        for (int ks = 0; ks < 2; ks++) {
            uint32_t a[2][4];
#pragma unroll
            for (int mt = 0; mt < 2; mt++) {
                uint32_t ad = sA + (wm + mt * 16 + lrow) * 80 + (ks * 16 + lkB) * 2;
                LDMX4(a[mt][0], a[mt][1], a[mt][2], a[mt][3], ad);
            }
            uint32_t b[4][4];
#pragma unroll
            for (int g = 0; g < 4; g++) {
                uint32_t bd = sB + (wn + g * 16 + lrow) * 80 + (ks * 16 + lkB) * 2;
                LDMX4(b[g][0], b[g][1], b[g][2], b[g][3], bd);
            }
#pragma unroll
            for (int mt = 0; mt < 2; mt++)
#pragma unroll
                for (int g = 0; g < 4; g++) {
                    MMAF16(acc[mt][2 * g],
                           a[mt][0], a[mt][1], a[mt][2], a[mt][3],
                           b[g][0], b[g][2]);
                    MMAF16(acc[mt][2 * g + 1],
                           a[mt][0], a[mt][1], a[mt][2], a[mt][3],
                           b[g][1], b[g][3]);
                }
        }
    }
    __syncthreads();
}

// =================================================================================
// GEMM kernels
// =================================================================================
#define TSTR 130   // transpose staging stride (halfs): odd word stride -> conflict-free 32-bit

__global__ void __launch_bounds__(256, 2) proj_tc(int mode) {
    extern __shared__ __align__(128) char smem[];
    float acc[2][8][4];
#pragma unroll
    for (int i = 0; i < 2; i++)
#pragma unroll
        for (int j = 0; j < 8; j++)
#pragma unroll
            for (int c = 0; c < 4; c++) acc[i][j][c] = 0.0f;

    const int m0 = blockIdx.y * 128;
    const int n0 = blockIdx.x * 128;
    gemm1(g_xf + (size_t)m0 * HID,
          g_wf[mode] + (size_t)n0 * HID,
          HID, HID, HID / CHUNK_K, smem_u32(smem), acc);

    const int tid = threadIdx.x, wid = tid >> 5, lane = tid & 31;
    const int wm = (wid & 3) * 32, wn = (wid >> 2) * 64;
    const int g = lane >> 2, t2 = (lane & 3) * 2;

    if (mode != 2) {
        __half* dst = (mode == 0) ? g_qf : g_kf;
#pragma unroll
        for (int mt = 0; mt < 2; mt++)
#pragma unroll
            for (int ng = 0; ng < 8; ng++)
#pragma unroll
                for (int ci = 0; ci < 4; ci++) {
                    int m = m0 + wm + mt * 16 + g + ((ci >> 1) << 3);
                    int n = n0 + wn + ng * 8 + t2 + (ci & 1);
                    dst[(size_t)m * HID + n] = __float2half_rn(acc[mt][ng][ci]);
                }
    } else {
        // fused transpose: stage tile into smem as [n_local][m_local], then write v^T
        __half* ts = (__half*)smem;
#pragma unroll
        for (int mt = 0; mt < 2; mt++)
#pragma unroll
            for (int ng = 0; ng < 8; ng++)
#pragma unroll
                for (int ci = 0; ci < 4; ci++) {
                    int ml = wm + mt * 16 + g + ((ci >> 1) << 3);
                    int nl = wn + ng * 8 + t2 + (ci & 1);
                    ts[nl * TSTR + ml] = __float2half_rn(acc[mt][ng][ci]);
                }
        __syncthreads();
        const int b  = m0 >> 12;            // batch of this m-tile
        const int s0 = m0 & (SLEN - 1);     // seq offset within batch
        const int r    = tid & 127;         // h row within tile
        const int part = tid >> 7;          // 0/1 -> 64-half halves
        __half* drow = g_vt + ((size_t)b * HID + n0 + r) * SLEN + s0 + part * 64;
        const __half* srow = ts + r * TSTR + part * 64;
        // shared side: scalar 32-bit loads (4B aligned); global side: 16B stores
#pragma unroll
        for (int k = 0; k < 8; k++) {
            uint32_t v0, v1, v2, v3;
            uint32_t ad = smem_u32(srow + k * 8);
            asm volatile("ld.shared.b32 %0, [%1];"      : "=r"(v0) : "r"(ad));
            asm volatile("ld.shared.b32 %0, [%1+4];"    : "=r"(v1) : "r"(ad));
            asm volatile("ld.shared.b32 %0, [%1+8];"    : "=r"(v2) : "r"(ad));
            asm volatile("ld.shared.b32 %0, [%1+12];"   : "=r"(v3) : "r"(ad));
            *(uint4*)(drow + k * 8) = make_uint4(v0, v1, v2, v3);
        }
    }
}

__global__ void __launch_bounds__(256, 2) scores_tc() {
    const int m0 = blockIdx.y * 128;
    const int n0 = blockIdx.x * 128;
    if (n0 > m0 + 127) return;                 // fully masked tile
    const int b = blockIdx.z;

    extern __shared__ __align__(128) char smem[];
    float acc[2][8][4];
#pragma unroll
    for (int i = 0; i < 2; i++)
#pragma unroll
        for (int j = 0; j < 8; j++)
#pragma unroll
            for (int c = 0; c < 4; c++) acc[i][j][c] = 0.0f;

    gemm1(g_qf + (size_t)(b * SLEN + m0) * HID,
          g_kf + (size_t)(b * SLEN + n0) * HID,
          HID, HID, HID / CHUNK_K, smem_u32(smem), acc);

    const float scale = 0.03125f;   // 1/sqrt(1024)
    const int tid = threadIdx.x, wid = tid >> 5, lane = tid & 31;
    const int wm = (wid & 3) * 32, wn = (wid >> 2) * 64;
    const int g = lane >> 2, t2 = (lane & 3) * 2;
#pragma unroll
    for (int mt = 0; mt < 2; mt++)
#pragma unroll
        for (int ng = 0; ng < 8; ng++)
#pragma unroll
            for (int ci2 = 0; ci2 < 2; ci2++) {
                int m = m0 + wm + mt * 16 + g + ci2 * 8;
                int n = n0 + wn + ng * 8 + t2;
                __half2 h = __floats2half2_rn(acc[mt][ng][2 * ci2] * scale,
                                              acc[mt][ng][2 * ci2 + 1] * scale);
                *(__half2*)(g_Sh + ((size_t)b * SLEN + m) * SLEN + n) = h;
            }
}

__global__ void __launch_bounds__(256, 2) pv_tc(float* __restrict__ out) {
    extern __shared__ __align__(128) char smem[];
    float acc[2][8][4];
#pragma unroll
    for (int i = 0; i < 2; i++)
#pragma unroll
        for (int j = 0; j < 8; j++)
#pragma unroll
            for (int c = 0; c < 4; c++) acc[i][j][c] = 0.0f;

    const int n0 = blockIdx.x * 128;
    const int m0 = (int)(gridDim.y - 1 - blockIdx.y) * 128;   // heavy tiles first
    const int b  = blockIdx.z;
    const int nc = (m0 + 128) / CHUNK_K;

    gemm1(g_pf + (size_t)(b * SLEN + m0) * SLEN,
          g_vt + (size_t)(b * HID + n0) * SLEN,
          SLEN, SLEN, nc, smem_u32(smem), acc);

    const int tid = threadIdx.x, wid = tid >> 5, lane = tid & 31;
    const int wm = (wid & 3) * 32, wn = (wid >> 2) * 64;
    const int g = lane >> 2, t2 = (lane & 3) * 2;
#pragma unroll
    for (int mt = 0; mt < 2; mt++)
#pragma unroll
        for (int ng = 0; ng < 8; ng++)
#pragma unroll
            for (int ci2 = 0; ci2 < 2; ci2++) {
                int m = m0 + wm + mt * 16 + g + ci2 * 8;
                int n = n0 + wn + ng * 8 + t2;
                float2 v = make_float2(acc[mt][ng][2 * ci2], acc[mt][ng][2 * ci2 + 1]);
                *(float2*)(out + ((size_t)b * SLEN + m) * HID + n) = v;
            }
}

// ---------------- softmax: Sh (scaled fp16) -> p fp16, single global pass ----------------
__global__ void __launch_bounds__(256) softmax_kernel() {
    __shared__ float red[16];
    const int row = blockIdx.x;
    const int i   = row & (SLEN - 1);
    const int tid = threadIdx.x, wid = tid >> 5, lane = tid & 31;
    const int n    = i + 1;
    const int jpad = ((i >> 7) + 1) << 7;
    const __half2* srow2 = (const __half2*)(g_Sh + (size_t)row * SLEN);

    float2 v[8];
    float lm = -3.0e38f;
#pragma unroll
    for (int it = 0; it < 8; it++) {
        int j2 = tid + 256 * it;
        int j  = 2 * j2;
        if (j < n) {
            float2 f = __half22float2(srow2[j2]);
            if (j + 1 >= n) f.y = -3.0e38f;
            v[it] = f;
            lm = fmaxf(lm, fmaxf(f.x, f.y));
        } else {
            v[it] = make_float2(-3.0e38f, -3.0e38f);
        }
    }
#pragma unroll
    for (int o = 16; o; o >>= 1) lm = fmaxf(lm, __shfl_xor_sync(0xffffffffu, lm, o));
    if (lane == 0) red[wid] = lm;
    __syncthreads();
    if (tid == 0) {
        float m = red[0];
#pragma unroll
        for (int w = 1; w < 8; w++) m = fmaxf(m, red[w]);
        red[0] = m;
    }
    __syncthreads();
    const float mx = red[0];

    float ls = 0.0f;
#pragma unroll
    for (int it = 0; it < 8; it++) {
        float ex = (v[it].x > -1.0e38f) ? __expf(v[it].x - mx) : 0.0f;
        float ey = (v[it].y > -1.0e38f) ? __expf(v[it].y - mx) : 0.0f;
        v[it].x = ex; v[it].y = ey;
        ls += ex + ey;
    }
#pragma unroll
    for (int o = 16; o; o >>= 1) ls += __shfl_xor_sync(0xffffffffu, ls, o);
    if (lane == 0) red[8 + wid] = ls;
    __syncthreads();
    if (tid == 0) {
        float s = 0.0f;
#pragma unroll
        for (int w = 0; w < 8; w++) s += red[8 + w];
        red[8] = 1.0f / s;
    }
    __syncthreads();
    const float inv = red[8];

    __half2* pf2 = (__half2*)(g_pf + (size_t)row * SLEN);
#pragma unroll
    for (int it = 0; it < 8; it++) {
        int j2 = tid + 256 * it;
        if (2 * j2 < jpad)
            pf2[j2] = __floats2half2_rn(v[it].x * inv, v[it].y * inv);
    }
}

// ---------------- input conversions (vectorized: 4 elems/thread) ----------------
__global__ void __launch_bounds__(256) conv_x(const float* __restrict__ x) {
    size_t i4 = (size_t)blockIdx.x * 256 + threadIdx.x;
    float4 v = ((const float4*)x)[i4];
    __half2 h0 = __floats2half2_rn(v.x, v.y);
    __half2 h1 = __floats2half2_rn(v.z, v.w);
    ((uint2*)g_xf)[i4] = make_uint2(*(uint32_t*)&h0, *(uint32_t*)&h1);
}

__global__ void __launch_bounds__(256) conv_w(const float* __restrict__ W, int which) {
    size_t i4 = (size_t)blockIdx.x * 256 + threadIdx.x;
    float4 v = ((const float4*)W)[i4];
    __half2 h0 = __floats2half2_rn(v.x, v.y);
    __half2 h1 = __floats2half2_rn(v.z, v.w);
    ((uint2*)g_wf[which])[i4] = make_uint2(*(uint32_t*)&h0, *(uint32_t*)&h1);
}

// =================================================================================
// Launch (launch index 5 = scores_tc: profiled by ncu -s 5 -c 1)
// =================================================================================
extern "C" void kernel_launch(void* const* d_in, const int* in_sizes, int n_in,
                              void* d_out, int out_size) {
    (void)in_sizes; (void)n_in; (void)out_size;
    const float* x  = (const float*)d_in[0];
    const float* Wq = (const float*)d_in[1];
    const float* Wk = (const float*)d_in[2];
    const float* Wv = (const float*)d_in[3];
    float* out = (float*)d_out;

    static bool attr_set = false;
    if (!attr_set) {
        cudaFuncSetAttribute(proj_tc,   cudaFuncAttributeMaxDynamicSharedMemorySize, E1_SMEM);
        cudaFuncSetAttribute(scores_tc, cudaFuncAttributeMaxDynamicSharedMemorySize, E1_SMEM);
        cudaFuncSetAttribute(pv_tc,     cudaFuncAttributeMaxDynamicSharedMemorySize, E1_SMEM);
        attr_set = true;
    }

    dim3 pgrid(HID / 128, MTOT / 128);                 // (8, 128)

    conv_x<<<(MTOT * HID / 4) / 256, 256>>>(x);        // 0
    conv_w<<<(HID * HID / 4) / 256, 256>>>(Wq, 0);     // 1
    conv_w<<<(HID * HID / 4) / 256, 256>>>(Wk, 1);     // 2
    proj_tc<<<pgrid, 256, E1_SMEM>>>(0);               // 3  -> q
    proj_tc<<<pgrid, 256, E1_SMEM>>>(1);               // 4  -> k
    scores_tc<<<dim3(SLEN / 128, SLEN / 128, BATCH), 256, E1_SMEM>>>();   // 5 (profiled)
    conv_w<<<(HID * HID / 4) / 256, 256>>>(Wv, 2);     // 6
    proj_tc<<<pgrid, 256, E1_SMEM>>>(2);               // 7  -> v^T (fused transpose)
    softmax_kernel<<<MTOT, 256>>>();                   // 8
    pv_tc<<<dim3(HID / 128, SLEN / 128, BATCH), 256, E1_SMEM>>>(out);     // 9
}